// round 3
// baseline (speedup 1.0000x reference)
#include <cuda_runtime.h>
#include <cuda_bf16.h>
#include <cstdint>
#include <cstring>

// ============================ problem constants ============================
constexpr int IMGC = 224;
constexpr int KTOT = IMGC * IMGC;          // 50176
constexpr int BQ   = 256;                  // batch
constexpr int JN   = 25;
constexpr int TN   = 64;
constexpr int OUTN = 256;
constexpr int MIDJ = JN / 2;               // 12
constexpr int BOXC = 20;

constexpr int CHUNK_K  = 64;               // bf16 elems per K-chunk (128B rows)
constexpr int NCH_TOT  = KTOT / CHUNK_K;   // 784
constexpr int KSPLIT   = 74;               // 2 x 74 = 148 CTAs = one full wave

// ============================ smem layout (dynamic) ========================
// A: 128 rows x 128B = 16KB, BH/BL: 256 rows x 128B = 32KB each; x2 buffers
constexpr uint32_t OFF_A0   = 0;
constexpr uint32_t OFF_A1   = OFF_A0  + 16384;
constexpr uint32_t OFF_BH0  = OFF_A1  + 16384;        // 32768
constexpr uint32_t OFF_BH1  = OFF_BH0 + 32768;
constexpr uint32_t OFF_BL0  = OFF_BH1 + 32768;
constexpr uint32_t OFF_BL1  = OFF_BL0 + 32768;
constexpr uint32_t SMEM_TOTAL = OFF_BL1 + 32768;      // 163840

// ============================ scratch (device globals) =====================
__device__ __align__(256) __nv_bfloat16 g_mask[(size_t)BQ * KTOT];        // 25.7 MB
__device__ __align__(256) float g_partial[(size_t)KSPLIT * BQ * OUTN];    // 19.4 MB
__device__ int g_px[BQ * JN];
__device__ int g_ylo[BQ * JN];
__device__ int g_yhi[BQ * JN];

// ============================ PTX helpers ==================================
__device__ __forceinline__ uint32_t smem_u32(const void* p) {
    uint32_t a;
    asm("{ .reg .u64 t; cvta.to.shared.u64 t, %1; cvt.u32.u64 %0, t; }"
        : "=r"(a) : "l"(p));
    return a;
}

#define SWZ128(off) ((off) ^ (((off) >> 3) & 0x70))

__device__ __forceinline__ void cp_async16(uint32_t dst, const void* src) {
    asm volatile("cp.async.cg.shared.global [%0], [%1], 16;\n"
                 :: "r"(dst), "l"(src) : "memory");
}
__device__ __forceinline__ void cp_async_wait_all() {
    asm volatile("cp.async.commit_group;\n"
                 "cp.async.wait_group 0;\n" ::: "memory");
}

__device__ __forceinline__ void ldsm_x4(uint32_t* r, uint32_t addr) {
    asm volatile("ldmatrix.sync.aligned.m8n8.x4.shared.b16 {%0,%1,%2,%3}, [%4];\n"
                 : "=r"(r[0]), "=r"(r[1]), "=r"(r[2]), "=r"(r[3]) : "r"(addr));
}

__device__ __forceinline__ void mma_bf16(float* c, const uint32_t* a,
                                         uint32_t b0, uint32_t b1) {
    asm volatile(
        "mma.sync.aligned.m16n8k16.row.col.f32.bf16.bf16.f32 "
        "{%0,%1,%2,%3}, {%4,%5,%6,%7}, {%8,%9}, {%0,%1,%2,%3};\n"
        : "+f"(c[0]), "+f"(c[1]), "+f"(c[2]), "+f"(c[3])
        : "r"(a[0]), "r"(a[1]), "r"(a[2]), "r"(a[3]), "r"(b0), "r"(b1));
}

// ============================ kernel 1: per-(b,j) farthest-frame box =======
__global__ void prep_kernel(const float* __restrict__ sk) {
    int id = blockIdx.x * blockDim.x + threadIdx.x;
    if (id >= BQ * JN) return;
    int b = id / JN, j = id % JN;
    const float* base = sk + ((size_t)b * JN + j) * TN * 3;
    const float* midb = sk + ((size_t)b * JN + MIDJ) * TN * 3;

    float best = -1.0f;
    int   tb = 0;
    for (int t = 0; t < TN; t++) {
        float dx = base[t * 3 + 0] - midb[t * 3 + 0];
        float dy = base[t * 3 + 1] - midb[t * 3 + 1];
        float dz = base[t * 3 + 2] - midb[t * 3 + 2];
        float d2 = __fadd_rn(__fadd_rn(__fmul_rn(dx, dx), __fmul_rn(dy, dy)),
                             __fmul_rn(dz, dz));
        float d = __fsqrt_rn(d2);
        if (d > best) { best = d; tb = t; }   // first-max == argmax semantics
    }
    float x = base[tb * 3 + 0];
    float y = base[tb * 3 + 1];
    int px = (int)(__fmul_rn(x, 224.0f));     // truncation == astype(int32)
    int py = (int)(__fmul_rn(y, 224.0f));
    g_px[id]  = px;
    g_ylo[id] = (py < BOXC) ? 0 : py - BOXC;
    g_yhi[id] = (py > IMGC - BOXC) ? IMGC : py + BOXC;
}

// ============================ kernel 2: bf16 mask ===========================
__global__ void mask_kernel() {
    const int x = blockIdx.x;     // first IMG axis (px window)
    const int b = blockIdx.y;
    const int y = threadIdx.x;    // second IMG axis (py window)

    __shared__ int spx[JN], slo[JN], shi[JN];
    if (y < JN) {
        spx[y] = g_px[b * JN + y];
        slo[y] = g_ylo[b * JN + y];
        shi[y] = g_yhi[b * JN + y];
    }
    __syncthreads();

    int v = 0;
#pragma unroll
    for (int j = 0; j < JN; j++) {
        if (j == MIDJ) continue;
        int hit = (x >= spx[j] - BOXC) & (x < spx[j] + BOXC) &
                  (y >= slo[j]) & (y < shi[j]);
        v |= hit;
    }
    g_mask[(size_t)b * KTOT + x * IMGC + y] =
        v ? __float2bfloat16(1.0f) : __float2bfloat16(0.0f);
}

// ============================ kernel 3: split-K mma.sync GEMM ===============
// grid (2, KSPLIT): blockIdx.x = M tile (128 batches), blockIdx.y = K split.
// 512 threads = 16 warps in 4(M) x 4(N) grid; warp tile 32 x 64.
// A = mask [128 x 64] bf16 (cp.async), B = W [256 x 64] fp32 -> bf16 hi+lo.
// Both A and B are K-contiguous => both use NON-trans ldmatrix (row.col mma).
__global__ __launch_bounds__(512, 1)
void gemm_kernel(const float* __restrict__ W) {
    extern __shared__ char smem[];
    const uint32_t sb = smem_u32(smem);
    const int tid = threadIdx.x;
    const int m0  = blockIdx.x * 128;

    const int c0 = (int)(((long long)blockIdx.y * NCH_TOT) / KSPLIT);
    const int c1 = (int)(((long long)(blockIdx.y + 1) * NCH_TOT) / KSPLIT);

    const int wid = tid >> 5;
    const int lid = tid & 31;
    const int wm  = wid >> 2;           // 0..3  -> m_base = wm*32
    const int wn  = wid & 3;            // 0..3  -> n_base = wn*64
    const int m_base = wm * 32;
    const int n_base = wn * 64;

    // per-lane ldmatrix logical offsets (before swizzle, before k-step)
    // non-trans x4: lanes 0-7 -> mat0 rows, 8-15 -> mat1, 16-23 -> mat2, 24-31 -> mat3
    uint32_t rowA[2], rowB[4];
#pragma unroll
    for (int mt = 0; mt < 2; mt++)
        rowA[mt] = (uint32_t)((m_base + mt * 16 + (lid & 15)) * 128 +
                              ((lid >> 4) * 16));
    // B mats per 16-row group: mat0 = n0-7 k0-7, mat1 = n0-7 k8-15,
    //                          mat2 = n8-15 k0-7, mat3 = n8-15 k8-15
#pragma unroll
    for (int np = 0; np < 4; np++)
        rowB[np] = (uint32_t)((n_base + np * 16 + ((lid >> 4) << 3) + (lid & 7)) * 128 +
                              (((lid >> 3) & 1) << 4));

    float acc[2][8][4];
#pragma unroll
    for (int mt = 0; mt < 2; mt++)
#pragma unroll
        for (int nt = 0; nt < 8; nt++)
#pragma unroll
            for (int z = 0; z < 4; z++) acc[mt][nt][z] = 0.0f;

    // B producer indexing: 8 float4 per thread, u = tid + r*512
    // row = u>>4 (0..255), c = u&15 (float4 col)
    float4 wreg[8];

    // ---- prologue: stage chunk c0 into buffer 0 ----
    {
        const int kk = c0 * CHUNK_K;
#pragma unroll
        for (int r = 0; r < 2; r++) {
            int u = tid + r * 512;
            int row = u >> 3, c = u & 7;
            cp_async16(sb + OFF_A0 + SWZ128((uint32_t)(row * 128 + c * 16)),
                       &g_mask[(size_t)(m0 + row) * KTOT + kk + c * 8]);
        }
#pragma unroll
        for (int r = 0; r < 8; r++) {
            int u = tid + r * 512;
            int row = u >> 4, c = u & 15;
            wreg[r] = *reinterpret_cast<const float4*>(
                &W[(size_t)row * KTOT + kk + c * 4]);
        }
#pragma unroll
        for (int r = 0; r < 8; r++) {
            int u = tid + r * 512;
            int row = u >> 4, c = u & 15;
            __nv_bfloat162 h01 = __float22bfloat162_rn(make_float2(wreg[r].x, wreg[r].y));
            __nv_bfloat162 h23 = __float22bfloat162_rn(make_float2(wreg[r].z, wreg[r].w));
            float2 hf01 = __bfloat1622float2(h01);
            float2 hf23 = __bfloat1622float2(h23);
            __nv_bfloat162 l01 = __float22bfloat162_rn(
                make_float2(wreg[r].x - hf01.x, wreg[r].y - hf01.y));
            __nv_bfloat162 l23 = __float22bfloat162_rn(
                make_float2(wreg[r].z - hf23.x, wreg[r].w - hf23.y));
            uint2 vh, vl;
            memcpy(&vh.x, &h01, 4); memcpy(&vh.y, &h23, 4);
            memcpy(&vl.x, &l01, 4); memcpy(&vl.y, &l23, 4);
            uint32_t so = SWZ128((uint32_t)(row * 128 + c * 8));
            *reinterpret_cast<uint2*>(smem + OFF_BH0 + so) = vh;
            *reinterpret_cast<uint2*>(smem + OFF_BL0 + so) = vl;
        }
        cp_async_wait_all();
    }

    for (int i = c0; i < c1; i++) {
        const int s = (i - c0) & 1;
        const uint32_t a_off  = s ? OFF_A1  : OFF_A0;
        const uint32_t bh_off = s ? OFF_BH1 : OFF_BH0;
        const uint32_t bl_off = s ? OFF_BL1 : OFF_BL0;
        const uint32_t a_nx   = s ? OFF_A0  : OFF_A1;
        const uint32_t bh_nx  = s ? OFF_BH0 : OFF_BH1;
        const uint32_t bl_nx  = s ? OFF_BL0 : OFF_BL1;
        const bool more = (i + 1 < c1);

        __syncthreads();   // buf s published; buf s^1 free

        if (more) {
            const int kk = (i + 1) * CHUNK_K;
#pragma unroll
            for (int r = 0; r < 2; r++) {
                int u = tid + r * 512;
                int row = u >> 3, c = u & 7;
                cp_async16(sb + a_nx + SWZ128((uint32_t)(row * 128 + c * 16)),
                           &g_mask[(size_t)(m0 + row) * KTOT + kk + c * 8]);
            }
#pragma unroll
            for (int r = 0; r < 8; r++) {
                int u = tid + r * 512;
                int row = u >> 4, c = u & 15;
                wreg[r] = *reinterpret_cast<const float4*>(
                    &W[(size_t)row * KTOT + kk + c * 4]);
            }
        }

        // ---- compute chunk i from buf s ----
#pragma unroll
        for (int ks = 0; ks < 4; ks++) {
            uint32_t a[2][4];
            ldsm_x4(a[0], sb + a_off + SWZ128(rowA[0] + ks * 32));
            ldsm_x4(a[1], sb + a_off + SWZ128(rowA[1] + ks * 32));
#pragma unroll
            for (int np = 0; np < 4; np++) {
                uint32_t b[4];
                ldsm_x4(b, sb + bh_off + SWZ128(rowB[np] + ks * 32));
                mma_bf16(acc[0][np * 2 + 0], a[0], b[0], b[1]);
                mma_bf16(acc[0][np * 2 + 1], a[0], b[2], b[3]);
                mma_bf16(acc[1][np * 2 + 0], a[1], b[0], b[1]);
                mma_bf16(acc[1][np * 2 + 1], a[1], b[2], b[3]);
            }
#pragma unroll
            for (int np = 0; np < 4; np++) {
                uint32_t b[4];
                ldsm_x4(b, sb + bl_off + SWZ128(rowB[np] + ks * 32));
                mma_bf16(acc[0][np * 2 + 0], a[0], b[0], b[1]);
                mma_bf16(acc[0][np * 2 + 1], a[0], b[2], b[3]);
                mma_bf16(acc[1][np * 2 + 0], a[1], b[0], b[1]);
                mma_bf16(acc[1][np * 2 + 1], a[1], b[2], b[3]);
            }
        }

        if (more) {
#pragma unroll
            for (int r = 0; r < 8; r++) {
                int u = tid + r * 512;
                int row = u >> 4, c = u & 15;
                __nv_bfloat162 h01 = __float22bfloat162_rn(make_float2(wreg[r].x, wreg[r].y));
                __nv_bfloat162 h23 = __float22bfloat162_rn(make_float2(wreg[r].z, wreg[r].w));
                float2 hf01 = __bfloat1622float2(h01);
                float2 hf23 = __bfloat1622float2(h23);
                __nv_bfloat162 l01 = __float22bfloat162_rn(
                    make_float2(wreg[r].x - hf01.x, wreg[r].y - hf01.y));
                __nv_bfloat162 l23 = __float22bfloat162_rn(
                    make_float2(wreg[r].z - hf23.x, wreg[r].w - hf23.y));
                uint2 vh, vl;
                memcpy(&vh.x, &h01, 4); memcpy(&vh.y, &h23, 4);
                memcpy(&vl.x, &l01, 4); memcpy(&vl.y, &l23, 4);
                uint32_t so = SWZ128((uint32_t)(row * 128 + c * 8));
                *reinterpret_cast<uint2*>(smem + bh_nx + so) = vh;
                *reinterpret_cast<uint2*>(smem + bl_nx + so) = vl;
            }
            cp_async_wait_all();
        }
    }

    // ---- epilogue: write fp32 partials ----
    float* base = &g_partial[((size_t)blockIdx.y * 256 + m0) * 256];
#pragma unroll
    for (int mt = 0; mt < 2; mt++) {
#pragma unroll
        for (int nt = 0; nt < 8; nt++) {
            int m = m_base + mt * 16 + (lid >> 2);
            int n = n_base + nt * 8 + (lid & 3) * 2;
            float2 v0 = make_float2(acc[mt][nt][0], acc[mt][nt][1]);
            float2 v1 = make_float2(acc[mt][nt][2], acc[mt][nt][3]);
            *reinterpret_cast<float2*>(base + (size_t)m * 256 + n) = v0;
            *reinterpret_cast<float2*>(base + (size_t)(m + 8) * 256 + n) = v1;
        }
    }
}

// ============================ kernel 4: reduce + bias + rgb multiply ========
__global__ void reduce_kernel(const float* __restrict__ rgb,
                              const float* __restrict__ bias,
                              float* __restrict__ out) {
    const int b = blockIdx.x;
    const int o = threadIdx.x;
    float acc = 0.0f;
#pragma unroll 8
    for (int s = 0; s < KSPLIT; s++)
        acc += g_partial[(size_t)s * (BQ * OUTN) + b * OUTN + o];
    out[b * OUTN + o] = rgb[b * OUTN + o] * (acc + bias[o]);
}

// ============================ launch ========================================
extern "C" void kernel_launch(void* const* d_in, const int* in_sizes, int n_in,
                              void* d_out, int out_size) {
    // identify inputs by element count:
    // rgbfuture 65536, skeleton 1228800, W 12845056, b 256
    const float* rgb = nullptr;
    const float* sk  = nullptr;
    const float* W   = nullptr;
    const float* bias = nullptr;
    for (int i = 0; i < n_in; i++) {
        switch (in_sizes[i]) {
            case BQ * OUTN:          rgb  = (const float*)d_in[i]; break;
            case BQ * JN * TN * 3:   sk   = (const float*)d_in[i]; break;
            case OUTN * KTOT:        W    = (const float*)d_in[i]; break;
            case OUTN:               bias = (const float*)d_in[i]; break;
            default: break;
        }
    }
    float* out = (float*)d_out;

    cudaFuncSetAttribute(gemm_kernel,
                         cudaFuncAttributeMaxDynamicSharedMemorySize, SMEM_TOTAL);

    prep_kernel<<<(BQ * JN + 255) / 256, 256>>>(sk);
    mask_kernel<<<dim3(IMGC, BQ), IMGC>>>();
    gemm_kernel<<<dim3(2, KSPLIT), 512, SMEM_TOTAL>>>(W);
    reduce_kernel<<<BQ, OUTN>>>(rgb, bias, out);
}

// round 4
// speedup vs baseline: 1.0263x; 1.0263x over previous
#include <cuda_runtime.h>
#include <cuda_bf16.h>
#include <cstdint>
#include <cstring>

// ============================ problem constants ============================
constexpr int IMGC = 224;
constexpr int KTOT = IMGC * IMGC;          // 50176
constexpr int BQ   = 256;                  // batch
constexpr int JN   = 25;
constexpr int TN   = 64;
constexpr int OUTN = 256;
constexpr int MIDJ = JN / 2;               // 12
constexpr int BOXC = 20;

constexpr int CHUNK_K  = 64;               // bf16 elems per K-chunk (128B rows)
constexpr int NCH_TOT  = KTOT / CHUNK_K;   // 784
constexpr int KSPLIT   = 37;               // 2M x 2N x 37 = 148 CTAs = one wave

// ============================ smem layout (dynamic) ========================
// A: 128 x 128B = 16KB; BH/BL: 128 x 128B = 16KB each; double buffered.
constexpr uint32_t OFF_A0   = 0;
constexpr uint32_t OFF_A1   = 16384;
constexpr uint32_t OFF_BH0  = 32768;
constexpr uint32_t OFF_BH1  = 49152;
constexpr uint32_t OFF_BL0  = 65536;
constexpr uint32_t OFF_BL1  = 81920;
constexpr uint32_t SMEM_TOTAL = 98304;

// ============================ scratch (device globals) =====================
__device__ __align__(256) __nv_bfloat16 g_mask[(size_t)BQ * KTOT];        // 25.7 MB
__device__ __align__(256) float g_partial[(size_t)KSPLIT * BQ * OUTN];    // 9.7 MB
__device__ int g_px[BQ * JN];
__device__ int g_ylo[BQ * JN];
__device__ int g_yhi[BQ * JN];

// ============================ PTX helpers ==================================
__device__ __forceinline__ uint32_t smem_u32(const void* p) {
    uint32_t a;
    asm("{ .reg .u64 t; cvta.to.shared.u64 t, %1; cvt.u32.u64 %0, t; }"
        : "=r"(a) : "l"(p));
    return a;
}

#define SWZ128(off) ((off) ^ (((off) >> 3) & 0x70))

__device__ __forceinline__ void cp_async16(uint32_t dst, const void* src) {
    asm volatile("cp.async.cg.shared.global [%0], [%1], 16;\n"
                 :: "r"(dst), "l"(src) : "memory");
}
__device__ __forceinline__ void cp_async_wait_all() {
    asm volatile("cp.async.commit_group;\n"
                 "cp.async.wait_group 0;\n" ::: "memory");
}

__device__ __forceinline__ void ldsm_x4(uint32_t* r, uint32_t addr) {
    asm volatile("ldmatrix.sync.aligned.m8n8.x4.shared.b16 {%0,%1,%2,%3}, [%4];\n"
                 : "=r"(r[0]), "=r"(r[1]), "=r"(r[2]), "=r"(r[3]) : "r"(addr));
}

__device__ __forceinline__ void mma_bf16(float* c, const uint32_t* a,
                                         uint32_t b0, uint32_t b1) {
    asm volatile(
        "mma.sync.aligned.m16n8k16.row.col.f32.bf16.bf16.f32 "
        "{%0,%1,%2,%3}, {%4,%5,%6,%7}, {%8,%9}, {%0,%1,%2,%3};\n"
        : "+f"(c[0]), "+f"(c[1]), "+f"(c[2]), "+f"(c[3])
        : "r"(a[0]), "r"(a[1]), "r"(a[2]), "r"(a[3]), "r"(b0), "r"(b1));
}

// ============================ kernel 1: per-(b,j) farthest-frame box =======
__global__ void prep_kernel(const float* __restrict__ sk) {
    int id = blockIdx.x * blockDim.x + threadIdx.x;
    if (id >= BQ * JN) return;
    int b = id / JN, j = id % JN;
    const float* base = sk + ((size_t)b * JN + j) * TN * 3;
    const float* midb = sk + ((size_t)b * JN + MIDJ) * TN * 3;

    float best = -1.0f;
    int   tb = 0;
    for (int t = 0; t < TN; t++) {
        float dx = base[t * 3 + 0] - midb[t * 3 + 0];
        float dy = base[t * 3 + 1] - midb[t * 3 + 1];
        float dz = base[t * 3 + 2] - midb[t * 3 + 2];
        float d2 = __fadd_rn(__fadd_rn(__fmul_rn(dx, dx), __fmul_rn(dy, dy)),
                             __fmul_rn(dz, dz));
        float d = __fsqrt_rn(d2);
        if (d > best) { best = d; tb = t; }   // first-max == argmax semantics
    }
    float x = base[tb * 3 + 0];
    float y = base[tb * 3 + 1];
    int px = (int)(__fmul_rn(x, 224.0f));     // truncation == astype(int32)
    int py = (int)(__fmul_rn(y, 224.0f));
    g_px[id]  = px;
    g_ylo[id] = (py < BOXC) ? 0 : py - BOXC;
    g_yhi[id] = (py > IMGC - BOXC) ? IMGC : py + BOXC;
}

// ============================ kernel 2: bf16 mask ===========================
__global__ void mask_kernel() {
    const int x = blockIdx.x;     // first IMG axis (px window)
    const int b = blockIdx.y;
    const int y = threadIdx.x;    // second IMG axis (py window)

    __shared__ int spx[JN], slo[JN], shi[JN];
    if (y < JN) {
        spx[y] = g_px[b * JN + y];
        slo[y] = g_ylo[b * JN + y];
        shi[y] = g_yhi[b * JN + y];
    }
    __syncthreads();

    int v = 0;
#pragma unroll
    for (int j = 0; j < JN; j++) {
        if (j == MIDJ) continue;
        int hit = (x >= spx[j] - BOXC) & (x < spx[j] + BOXC) &
                  (y >= slo[j]) & (y < shi[j]);
        v |= hit;
    }
    g_mask[(size_t)b * KTOT + x * IMGC + y] =
        v ? __float2bfloat16(1.0f) : __float2bfloat16(0.0f);
}

// ============================ kernel 3: split-K mma.sync GEMM ===============
// grid (2, 2, KSPLIT): bx = M tile (128 rows), by = N tile (128 W rows),
// bz = K split. 512 threads = 16 warps in 4(M) x 4(N); warp tile 32 x 32.
// A = mask [128 x 64] bf16 (cp.async); B = W [128 x 64] fp32 -> bf16 hi+lo.
// ~90 regs/thread -> NO spills under the 128-reg cap (the R3 bug).
__global__ __launch_bounds__(512, 1)
void gemm_kernel(const float* __restrict__ W) {
    extern __shared__ char smem[];
    const uint32_t sb = smem_u32(smem);
    const int tid = threadIdx.x;
    const int m0  = blockIdx.x * 128;
    const int n0  = blockIdx.y * 128;

    const int c0 = (int)(((long long)blockIdx.z * NCH_TOT) / KSPLIT);
    const int c1 = (int)(((long long)(blockIdx.z + 1) * NCH_TOT) / KSPLIT);

    const int wid = tid >> 5;
    const int lid = tid & 31;
    const int m_base = (wid >> 2) * 32;
    const int n_base = (wid & 3) * 32;

    // per-lane ldmatrix logical offsets (pre-swizzle, pre-k-step)
    uint32_t rowA[2], rowB[2];
#pragma unroll
    for (int mt = 0; mt < 2; mt++)
        rowA[mt] = (uint32_t)((m_base + mt * 16 + (lid & 15)) * 128 +
                              ((lid >> 4) * 16));
#pragma unroll
    for (int np = 0; np < 2; np++)
        rowB[np] = (uint32_t)((n_base + np * 16 + ((lid >> 4) << 3) + (lid & 7)) * 128 +
                              (((lid >> 3) & 1) << 4));

    float acc[2][4][4];
#pragma unroll
    for (int mt = 0; mt < 2; mt++)
#pragma unroll
        for (int nt = 0; nt < 4; nt++)
#pragma unroll
            for (int z = 0; z < 4; z++) acc[mt][nt][z] = 0.0f;

    // B producer: 4 float4/thread; u = tid + r*512; row = u>>4, c = u&15
    float4 wreg[4];

    // ---- prologue: stage chunk c0 into buffer 0 ----
    {
        const int kk = c0 * CHUNK_K;
#pragma unroll
        for (int r = 0; r < 2; r++) {
            int u = tid + r * 512;
            int row = u >> 3, c = u & 7;
            cp_async16(sb + OFF_A0 + SWZ128((uint32_t)(row * 128 + c * 16)),
                       &g_mask[(size_t)(m0 + row) * KTOT + kk + c * 8]);
        }
#pragma unroll
        for (int r = 0; r < 4; r++) {
            int u = tid + r * 512;
            int row = u >> 4, c = u & 15;
            wreg[r] = *reinterpret_cast<const float4*>(
                &W[(size_t)(n0 + row) * KTOT + kk + c * 4]);
        }
#pragma unroll
        for (int r = 0; r < 4; r++) {
            int u = tid + r * 512;
            int row = u >> 4, c = u & 15;
            __nv_bfloat162 h01 = __float22bfloat162_rn(make_float2(wreg[r].x, wreg[r].y));
            __nv_bfloat162 h23 = __float22bfloat162_rn(make_float2(wreg[r].z, wreg[r].w));
            float2 hf01 = __bfloat1622float2(h01);
            float2 hf23 = __bfloat1622float2(h23);
            __nv_bfloat162 l01 = __float22bfloat162_rn(
                make_float2(wreg[r].x - hf01.x, wreg[r].y - hf01.y));
            __nv_bfloat162 l23 = __float22bfloat162_rn(
                make_float2(wreg[r].z - hf23.x, wreg[r].w - hf23.y));
            uint2 vh, vl;
            memcpy(&vh.x, &h01, 4); memcpy(&vh.y, &h23, 4);
            memcpy(&vl.x, &l01, 4); memcpy(&vl.y, &l23, 4);
            uint32_t so = SWZ128((uint32_t)(row * 128 + c * 8));
            *reinterpret_cast<uint2*>(smem + OFF_BH0 + so) = vh;
            *reinterpret_cast<uint2*>(smem + OFF_BL0 + so) = vl;
        }
        cp_async_wait_all();
    }

    for (int i = c0; i < c1; i++) {
        const int s = (i - c0) & 1;
        const uint32_t a_off  = s ? OFF_A1  : OFF_A0;
        const uint32_t bh_off = s ? OFF_BH1 : OFF_BH0;
        const uint32_t bl_off = s ? OFF_BL1 : OFF_BL0;
        const uint32_t a_nx   = s ? OFF_A0  : OFF_A1;
        const uint32_t bh_nx  = s ? OFF_BH0 : OFF_BH1;
        const uint32_t bl_nx  = s ? OFF_BL0 : OFF_BL1;
        const bool more = (i + 1 < c1);

        __syncthreads();   // buf s published; buf s^1 free

        if (more) {
            const int kk = (i + 1) * CHUNK_K;
#pragma unroll
            for (int r = 0; r < 2; r++) {
                int u = tid + r * 512;
                int row = u >> 3, c = u & 7;
                cp_async16(sb + a_nx + SWZ128((uint32_t)(row * 128 + c * 16)),
                           &g_mask[(size_t)(m0 + row) * KTOT + kk + c * 8]);
            }
#pragma unroll
            for (int r = 0; r < 4; r++) {
                int u = tid + r * 512;
                int row = u >> 4, c = u & 15;
                wreg[r] = *reinterpret_cast<const float4*>(
                    &W[(size_t)(n0 + row) * KTOT + kk + c * 4]);
            }
        }

        // ---- compute chunk i from buf s ----
#pragma unroll
        for (int ks = 0; ks < 4; ks++) {
            uint32_t a[2][4];
            ldsm_x4(a[0], sb + a_off + SWZ128(rowA[0] + ks * 32));
            ldsm_x4(a[1], sb + a_off + SWZ128(rowA[1] + ks * 32));
#pragma unroll
            for (int np = 0; np < 2; np++) {
                uint32_t b[4];
                ldsm_x4(b, sb + bh_off + SWZ128(rowB[np] + ks * 32));
                mma_bf16(acc[0][np * 2 + 0], a[0], b[0], b[1]);
                mma_bf16(acc[0][np * 2 + 1], a[0], b[2], b[3]);
                mma_bf16(acc[1][np * 2 + 0], a[1], b[0], b[1]);
                mma_bf16(acc[1][np * 2 + 1], a[1], b[2], b[3]);
            }
#pragma unroll
            for (int np = 0; np < 2; np++) {
                uint32_t b[4];
                ldsm_x4(b, sb + bl_off + SWZ128(rowB[np] + ks * 32));
                mma_bf16(acc[0][np * 2 + 0], a[0], b[0], b[1]);
                mma_bf16(acc[0][np * 2 + 1], a[0], b[2], b[3]);
                mma_bf16(acc[1][np * 2 + 0], a[1], b[0], b[1]);
                mma_bf16(acc[1][np * 2 + 1], a[1], b[2], b[3]);
            }
        }

        if (more) {
#pragma unroll
            for (int r = 0; r < 4; r++) {
                int u = tid + r * 512;
                int row = u >> 4, c = u & 15;
                __nv_bfloat162 h01 = __float22bfloat162_rn(make_float2(wreg[r].x, wreg[r].y));
                __nv_bfloat162 h23 = __float22bfloat162_rn(make_float2(wreg[r].z, wreg[r].w));
                float2 hf01 = __bfloat1622float2(h01);
                float2 hf23 = __bfloat1622float2(h23);
                __nv_bfloat162 l01 = __float22bfloat162_rn(
                    make_float2(wreg[r].x - hf01.x, wreg[r].y - hf01.y));
                __nv_bfloat162 l23 = __float22bfloat162_rn(
                    make_float2(wreg[r].z - hf23.x, wreg[r].w - hf23.y));
                uint2 vh, vl;
                memcpy(&vh.x, &h01, 4); memcpy(&vh.y, &h23, 4);
                memcpy(&vl.x, &l01, 4); memcpy(&vl.y, &l23, 4);
                uint32_t so = SWZ128((uint32_t)(row * 128 + c * 8));
                *reinterpret_cast<uint2*>(smem + bh_nx + so) = vh;
                *reinterpret_cast<uint2*>(smem + bl_nx + so) = vl;
            }
            cp_async_wait_all();
        }
    }

    // ---- epilogue: write fp32 partials ----
    float* base = &g_partial[((size_t)blockIdx.z * BQ + m0) * OUTN + n0];
#pragma unroll
    for (int mt = 0; mt < 2; mt++) {
#pragma unroll
        for (int nt = 0; nt < 4; nt++) {
            int m = m_base + mt * 16 + (lid >> 2);
            int n = n_base + nt * 8 + (lid & 3) * 2;
            float2 v0 = make_float2(acc[mt][nt][0], acc[mt][nt][1]);
            float2 v1 = make_float2(acc[mt][nt][2], acc[mt][nt][3]);
            *reinterpret_cast<float2*>(base + (size_t)m * OUTN + n) = v0;
            *reinterpret_cast<float2*>(base + (size_t)(m + 8) * OUTN + n) = v1;
        }
    }
}

// ============================ kernel 4: reduce + bias + rgb multiply ========
// grid BQ, 64 threads; one float4 of outputs per thread; partials L2-resident.
__global__ void reduce_kernel(const float* __restrict__ rgb,
                              const float* __restrict__ bias,
                              float* __restrict__ out) {
    const int b = blockIdx.x;
    const int o = threadIdx.x * 4;
    float4 acc = make_float4(0.f, 0.f, 0.f, 0.f);
    const float* p = &g_partial[b * OUTN + o];
#pragma unroll
    for (int s = 0; s < KSPLIT; s++) {
        float4 v = *reinterpret_cast<const float4*>(p + (size_t)s * (BQ * OUTN));
        acc.x += v.x; acc.y += v.y; acc.z += v.z; acc.w += v.w;
    }
    float4 bi = *reinterpret_cast<const float4*>(bias + o);
    float4 rg = *reinterpret_cast<const float4*>(rgb + b * OUTN + o);
    float4 res;
    res.x = rg.x * (acc.x + bi.x);
    res.y = rg.y * (acc.y + bi.y);
    res.z = rg.z * (acc.z + bi.z);
    res.w = rg.w * (acc.w + bi.w);
    *reinterpret_cast<float4*>(out + b * OUTN + o) = res;
}

// ============================ launch ========================================
extern "C" void kernel_launch(void* const* d_in, const int* in_sizes, int n_in,
                              void* d_out, int out_size) {
    const float* rgb = nullptr;
    const float* sk  = nullptr;
    const float* W   = nullptr;
    const float* bias = nullptr;
    for (int i = 0; i < n_in; i++) {
        switch (in_sizes[i]) {
            case BQ * OUTN:          rgb  = (const float*)d_in[i]; break;
            case BQ * JN * TN * 3:   sk   = (const float*)d_in[i]; break;
            case OUTN * KTOT:        W    = (const float*)d_in[i]; break;
            case OUTN:               bias = (const float*)d_in[i]; break;
            default: break;
        }
    }
    float* out = (float*)d_out;

    cudaFuncSetAttribute(gemm_kernel,
                         cudaFuncAttributeMaxDynamicSharedMemorySize, SMEM_TOTAL);

    prep_kernel<<<(BQ * JN + 255) / 256, 256>>>(sk);
    mask_kernel<<<dim3(IMGC, BQ), IMGC>>>();
    gemm_kernel<<<dim3(2, 2, KSPLIT), 512, SMEM_TOTAL>>>(W);
    reduce_kernel<<<BQ, 64>>>(rgb, bias, out);
}

// round 5
// speedup vs baseline: 1.7280x; 1.6837x over previous
#include <cuda_runtime.h>
#include <cstdint>

// ============================ problem constants ============================
constexpr int IMGC = 224;
constexpr int KTOT = IMGC * IMGC;     // 50176
constexpr int BQ   = 256;
constexpr int JN   = 25;
constexpr int TN   = 64;
constexpr int OUTN = 256;
constexpr int MIDJ = JN / 2;          // 12
constexpr int BOXC = 20;

constexpr int XG  = 32;               // x groups
constexpr int XPG = 7;                // x per group (32*7 = 224)
constexpr int NQ  = 4;                // n quarters of 64
constexpr uint32_t SMEM_MAIN = 224 * 64 * 4;   // 57344 B: S[224y][64n] swizzled

// ============================ scratch (device globals) =====================
__device__ __align__(256) unsigned long long g_bits[(size_t)IMGC * BQ * 4]; // 1.8MB
__device__ __align__(256) float g_part[(size_t)XG * BQ * OUTN];             // 8MB
__device__ int g_px[BQ * JN];
__device__ int g_ylo[BQ * JN];
__device__ int g_yhi[BQ * JN];

// ============================ kernel 1: farthest-frame box params ==========
__global__ void prep_kernel(const float* __restrict__ sk) {
    int id = blockIdx.x * blockDim.x + threadIdx.x;
    if (id >= BQ * JN) return;
    int b = id / JN, j = id % JN;
    const float* base = sk + ((size_t)b * JN + j) * TN * 3;
    const float* midb = sk + ((size_t)b * JN + MIDJ) * TN * 3;

    float best = -1.0f;
    int   tb = 0;
    for (int t = 0; t < TN; t++) {
        float dx = base[t * 3 + 0] - midb[t * 3 + 0];
        float dy = base[t * 3 + 1] - midb[t * 3 + 1];
        float dz = base[t * 3 + 2] - midb[t * 3 + 2];
        float d2 = __fadd_rn(__fadd_rn(__fmul_rn(dx, dx), __fmul_rn(dy, dy)),
                             __fmul_rn(dz, dz));
        float d = __fsqrt_rn(d2);
        if (d > best) { best = d; tb = t; }   // first-max == argmax semantics
    }
    float x = base[tb * 3 + 0];
    float y = base[tb * 3 + 1];
    int px = (int)(__fmul_rn(x, 224.0f));     // truncation == astype(int32)
    int py = (int)(__fmul_rn(y, 224.0f));
    g_px[id]  = px;
    g_ylo[id] = (py < BOXC) ? 0 : py - BOXC;
    g_yhi[id] = (py > IMGC - BOXC) ? IMGC : py + BOXC;
}

// ============================ kernel 2: per-(b,x) y-bitmask =================
// g_bits layout: [x][b][4 words] so the main kernel reads contiguously per x.
__global__ void bitmask_kernel() {
    const int x = blockIdx.x;
    const int b = threadIdx.x;

    unsigned long long m[4] = {0ull, 0ull, 0ull, 0ull};
#pragma unroll
    for (int j = 0; j < JN; j++) {
        if (j == MIDJ) continue;
        int px = g_px[b * JN + j];
        if (x >= px - BOXC && x < px + BOXC) {
            int lo = g_ylo[b * JN + j];
            int hi = g_yhi[b * JN + j];
#pragma unroll
            for (int w = 0; w < 4; w++) {
                int l = lo - w * 64;  if (l < 0)  l = 0;
                int h = hi - w * 64;  if (h > 64) h = 64;
                if (l < h) {
                    unsigned long long hiM = (h == 64) ? ~0ull : ((1ull << h) - 1ull);
                    unsigned long long loM = (1ull << l) - 1ull;
                    m[w] |= hiM & ~loM;
                }
            }
        }
    }
    unsigned long long* dst = g_bits + ((size_t)x * BQ + b) * 4;
    dst[0] = m[0]; dst[1] = m[1]; dst[2] = m[2]; dst[3] = m[3];
}

// ============================ kernel 3: scan + interval gather ==============
// grid (XG, NQ) = 128 CTAs, 512 threads.
// Per x: (a) 16 warps x 4 rows: coalesced W load, warp-shfl inclusive scan
// over y into swizzled smem S; (b) gather: thread = (b = tid/2, 32 n's in
// regs): walk run-end/run-start bits of the y-bitmask, acc += S[end],
// acc -= S[start-1]. Accumulate across 7 x's, write one fp32 partial.
// Swizzle: physical float4 index within a 64-float row = (f + y) & 15
// -> row base rotates with y, so same-column accesses spread across banks.
__global__ __launch_bounds__(512, 1)
void main_kernel(const float* __restrict__ W) {
    extern __shared__ float sS[];
    const int tid  = threadIdx.x;
    const int w    = tid >> 5;
    const int lane = tid & 31;
    const int xg   = blockIdx.x;
    const int nq   = blockIdx.y;
    const int n0   = nq * 64;
    const int b    = tid >> 1;
    const int half = tid & 1;

    float4 acc[8];
#pragma unroll
    for (int r = 0; r < 8; r++) acc[r] = make_float4(0.f, 0.f, 0.f, 0.f);

    for (int i = 0; i < XPG; i++) {
        const int x = xg * XPG + i;

        // ---- (a) load + inclusive scan along y, 4 rows per warp ----
        {
            const float* wp = W + (size_t)(n0 + w * 4) * KTOT + x * IMGC + lane;
            float v[4][7];
#pragma unroll
            for (int q = 0; q < 4; q++)
#pragma unroll
                for (int s = 0; s < 7; s++)
                    v[q][s] = wp[(size_t)q * KTOT + s * 32];

#pragma unroll
            for (int q = 0; q < 4; q++) {
                const int n = w * 4 + q;
                float carry = 0.f;
#pragma unroll
                for (int s = 0; s < 7; s++) {
                    float val = v[q][s];
#pragma unroll
                    for (int off = 1; off < 32; off <<= 1) {
                        float t = __shfl_up_sync(0xffffffffu, val, off);
                        if (lane >= off) val += t;
                    }
                    val += carry;
                    const int y = s * 32 + lane;
                    sS[y * 64 + ((((n >> 2) + y) & 15) << 2) + (n & 3)] = val;
                    carry = __shfl_sync(0xffffffffu, val, 31);
                }
            }
        }
        __syncthreads();

        // ---- (b) gather interval endpoint rows ----
        {
            const unsigned long long* bp = g_bits + ((size_t)x * BQ + b) * 4;
            const unsigned long long m0 = bp[0], m1 = bp[1], m2 = bp[2], m3 = bp[3];
            unsigned long long E[4], Sb[4];
            // run ends (last set bit of each run): +S[y]
            E[0] = m0 & ~((m0 >> 1) | (m1 << 63));
            E[1] = m1 & ~((m1 >> 1) | (m2 << 63));
            E[2] = m2 & ~((m2 >> 1) | (m3 << 63));
            E[3] = m3 & ~(m3 >> 1);
            // run starts: -S[y-1]; start at y==0 contributes nothing
            Sb[0] = m0 & ~(m0 << 1) & ~1ull;
            Sb[1] = m1 & ~((m1 << 1) | (m0 >> 63));
            Sb[2] = m2 & ~((m2 << 1) | (m1 >> 63));
            Sb[3] = m3 & ~((m3 << 1) | (m2 >> 63));

#pragma unroll
            for (int wd = 0; wd < 4; wd++) {
                unsigned long long e = E[wd];
                while (e) {
                    int p = __ffsll((long long)e) - 1; e &= e - 1;
                    int y = wd * 64 + p;
#pragma unroll
                    for (int r = 0; r < 8; r++) {
                        int f = half * 8 + r;
                        float4 t = *reinterpret_cast<const float4*>(
                            sS + y * 64 + (((f + y) & 15) << 2));
                        acc[r].x += t.x; acc[r].y += t.y;
                        acc[r].z += t.z; acc[r].w += t.w;
                    }
                }
                unsigned long long s = Sb[wd];
                while (s) {
                    int p = __ffsll((long long)s) - 1; s &= s - 1;
                    int y = wd * 64 + p - 1;
#pragma unroll
                    for (int r = 0; r < 8; r++) {
                        int f = half * 8 + r;
                        float4 t = *reinterpret_cast<const float4*>(
                            sS + y * 64 + (((f + y) & 15) << 2));
                        acc[r].x -= t.x; acc[r].y -= t.y;
                        acc[r].z -= t.z; acc[r].w -= t.w;
                    }
                }
            }
        }
        __syncthreads();   // S gets overwritten next x
    }

    float4* dst = reinterpret_cast<float4*>(
        g_part + ((size_t)xg * BQ + b) * OUTN + n0 + half * 32);
#pragma unroll
    for (int r = 0; r < 8; r++) dst[r] = acc[r];
}

// ============================ kernel 4: reduce + bias + rgb multiply ========
__global__ void final_kernel(const float* __restrict__ rgb,
                             const float* __restrict__ bias,
                             float* __restrict__ out) {
    const int b = blockIdx.x;
    const int o = threadIdx.x * 4;
    float4 acc = make_float4(0.f, 0.f, 0.f, 0.f);
    const float* p = g_part + b * OUTN + o;
#pragma unroll
    for (int s = 0; s < XG; s++) {
        float4 v = *reinterpret_cast<const float4*>(p + (size_t)s * (BQ * OUTN));
        acc.x += v.x; acc.y += v.y; acc.z += v.z; acc.w += v.w;
    }
    float4 bi = *reinterpret_cast<const float4*>(bias + o);
    float4 rg = *reinterpret_cast<const float4*>(rgb + b * OUTN + o);
    float4 res;
    res.x = rg.x * (acc.x + bi.x);
    res.y = rg.y * (acc.y + bi.y);
    res.z = rg.z * (acc.z + bi.z);
    res.w = rg.w * (acc.w + bi.w);
    *reinterpret_cast<float4*>(out + b * OUTN + o) = res;
}

// ============================ launch ========================================
extern "C" void kernel_launch(void* const* d_in, const int* in_sizes, int n_in,
                              void* d_out, int out_size) {
    const float* rgb = nullptr;
    const float* sk  = nullptr;
    const float* W   = nullptr;
    const float* bias = nullptr;
    for (int i = 0; i < n_in; i++) {
        switch (in_sizes[i]) {
            case BQ * OUTN:          rgb  = (const float*)d_in[i]; break;
            case BQ * JN * TN * 3:   sk   = (const float*)d_in[i]; break;
            case OUTN * KTOT:        W    = (const float*)d_in[i]; break;
            case OUTN:               bias = (const float*)d_in[i]; break;
            default: break;
        }
    }
    float* out = (float*)d_out;

    cudaFuncSetAttribute(main_kernel,
                         cudaFuncAttributeMaxDynamicSharedMemorySize, SMEM_MAIN);

    prep_kernel<<<(BQ * JN + 255) / 256, 256>>>(sk);
    bitmask_kernel<<<IMGC, BQ>>>();
    main_kernel<<<dim3(XG, NQ), 512, SMEM_MAIN>>>(W);
    final_kernel<<<BQ, 64>>>(rgb, bias, out);
}